// round 3
// baseline (speedup 1.0000x reference)
#include <cuda_runtime.h>

// Problem constants
#define NB     4
#define NP     1024
#define NKN    32
#define DIMC   256
#define HEADS  8
#define DH     64
#define DPG    32
#define INNERD 512
#define NPTS   (NB*NP)        // 4096 points
#define NTOK   (NPTS*NKN)     // 131072 tokens

typedef unsigned long long u64;

// ---------------- device scratch (no allocations allowed) ----------------
__device__ float g_sum[DIMC];
__device__ float g_sumsq[DIMC];
__device__ float g_scale[DIMC];
__device__ float g_shift[DIMC];
__device__ float g_oatt[(size_t)NTOK * INNERD];   // 268 MB attention output scratch

// ---------------- f32x2 packed helpers (sm_103a) ----------------
__device__ __forceinline__ u64 pack2(float a, float b) {
    u64 r;
    asm("mov.b64 %0, {%1,%2};" : "=l"(r) : "r"(__float_as_uint(a)), "r"(__float_as_uint(b)));
    return r;
}
__device__ __forceinline__ void unpack2(u64 v, float& a, float& b) {
    unsigned int lo, hi;
    asm("mov.b64 {%0,%1}, %2;" : "=r"(lo), "=r"(hi) : "l"(v));
    a = __uint_as_float(lo); b = __uint_as_float(hi);
}
__device__ __forceinline__ u64 ffma2(u64 a, u64 b, u64 c) {
    u64 d;
    asm("fma.rn.f32x2 %0, %1, %2, %3;" : "=l"(d) : "l"(a), "l"(b), "l"(c));
    return d;
}

// ---------------- K0: zero BN accumulators (graph replays need reset) ----------------
__global__ void bn_zero_kernel() {
    g_sum[threadIdx.x] = 0.f;
    g_sumsq[threadIdx.x] = 0.f;
}

// ---------------- K1: BN statistics (sum / sumsq per channel) ----------------
__global__ __launch_bounds__(256) void bn_stats_kernel(const float4* __restrict__ x4) {
    const int tid = threadIdx.x;
    const int c64 = tid & 63;          // which float4 of the 256-channel row
    const int rl  = tid >> 6;          // row lane 0..3
    const size_t base = (size_t)blockIdx.x * 256 + (size_t)rl * 64;
    float4 s = make_float4(0.f,0.f,0.f,0.f);
    float4 q = make_float4(0.f,0.f,0.f,0.f);
    #pragma unroll 4
    for (int i = 0; i < 64; ++i) {
        float4 v = x4[(base + i) * 64 + c64];
        s.x += v.x; s.y += v.y; s.z += v.z; s.w += v.w;
        q.x += v.x*v.x; q.y += v.y*v.y; q.z += v.z*v.z; q.w += v.w*v.w;
    }
    __shared__ float4 ss[256], qq[256];
    ss[tid] = s; qq[tid] = q;
    __syncthreads();
    if (tid < 64) {
        float4 a = ss[tid], b = ss[tid+64], c2 = ss[tid+128], d = ss[tid+192];
        float4 e = qq[tid], f = qq[tid+64], g2 = qq[tid+128], h = qq[tid+192];
        atomicAdd(&g_sum[tid*4+0], a.x+b.x+c2.x+d.x);
        atomicAdd(&g_sum[tid*4+1], a.y+b.y+c2.y+d.y);
        atomicAdd(&g_sum[tid*4+2], a.z+b.z+c2.z+d.z);
        atomicAdd(&g_sum[tid*4+3], a.w+b.w+c2.w+d.w);
        atomicAdd(&g_sumsq[tid*4+0], e.x+f.x+g2.x+h.x);
        atomicAdd(&g_sumsq[tid*4+1], e.y+f.y+g2.y+h.y);
        atomicAdd(&g_sumsq[tid*4+2], e.z+f.z+g2.z+h.z);
        atomicAdd(&g_sumsq[tid*4+3], e.w+f.w+g2.w+h.w);
    }
}

// ---------------- K2: BN finalize -> per-channel scale/shift ----------------
__global__ void bn_finalize_kernel(const float* __restrict__ gamma,
                                   const float* __restrict__ beta) {
    const int c = threadIdx.x;
    const float invN = 1.f / (float)NTOK;
    float m   = g_sum[c] * invN;
    float var = g_sumsq[c] * invN - m * m;
    float rstd = rsqrtf(var + 1e-5f);
    float sc = gamma[c] * rstd;
    g_scale[c] = sc;
    g_shift[c] = beta[c] - m * sc;
}

// ---------------- K3: fused per-point QKV + attention ----------------
// One block = one point (32 tokens x 256 channels). 256 threads.
// smem floats: xn 32*260 + W 3*2048 + qkv 3*32*68 + attn 32*36 = 22144 (88576 B)
#define ATTN_SMEM_BYTES (22144 * 4)

__global__ __launch_bounds__(256, 2) void attn_kernel(
    const float* __restrict__ x,
    const float* __restrict__ Wq,
    const float* __restrict__ Wk,
    const float* __restrict__ Wv)
{
    extern __shared__ float sm[];
    float* xn    = sm;                 // [32][260] normalized input (padded)
    float* Wqs   = xn + 32*260;        // [c][o] 32x64
    float* Wks   = Wqs + 2048;
    float* Wvs   = Wks + 2048;
    float* qs    = Wvs + 2048;         // [32][68]
    float* ks    = qs + 32*68;
    float* vs    = ks + 32*68;
    float* attnS = vs + 32*68;         // [32][36]

    const int tid = threadIdx.x;
    const int pt  = blockIdx.x;
    const float* xp = x + (size_t)pt * (NKN * DIMC);

    // Load & normalize: thread tid owns channel tid for all 32 tokens
    {
        const float sc = g_scale[tid];
        const float sh = g_shift[tid];
        #pragma unroll 8
        for (int tk = 0; tk < NKN; ++tk)
            xn[tk*260 + tid] = fmaf(xp[tk*DIMC + tid], sc, sh);
    }

    const int t = tid >> 3;   // token 0..31
    const int g = tid & 7;    // output octet 0..7 (o in [g*8, g*8+8))

    for (int h = 0; h < HEADS; ++h) {
        __syncthreads();   // xn ready (h==0) / previous head done reading smem
        // Stage weights [o][c] -> smem transposed [c][o]
        {
            const float* wqp = Wq + h*(DH*DPG);
            const float* wkp = Wk + h*(DH*DPG);
            const float* wvp = Wv + h*(DH*DPG);
            #pragma unroll
            for (int i = 0; i < 8; ++i) {
                int idx = tid + i*256;
                int o = idx >> 5, c = idx & 31;
                Wqs[c*64+o] = wqp[idx];
                Wks[c*64+o] = wkp[idx];
                Wvs[c*64+o] = wvp[idx];
            }
        }
        __syncthreads();

        // ---- q,k,v projection: thread computes 8 outputs of token t for each of q/k/v ----
        {
            float xv[DPG];
            const float* xrow = &xn[t*260 + h*DPG];
            #pragma unroll
            for (int c = 0; c < DPG; ++c) xv[c] = xrow[c];
            u64 aq[4] = {0,0,0,0}, ak[4] = {0,0,0,0}, av[4] = {0,0,0,0};
            #pragma unroll
            for (int c = 0; c < DPG; ++c) {
                u64 xx = pack2(xv[c], xv[c]);
                ulonglong2 wqa = *(const ulonglong2*)&Wqs[c*64 + g*8];
                ulonglong2 wqb = *(const ulonglong2*)&Wqs[c*64 + g*8 + 4];
                ulonglong2 wka = *(const ulonglong2*)&Wks[c*64 + g*8];
                ulonglong2 wkb = *(const ulonglong2*)&Wks[c*64 + g*8 + 4];
                ulonglong2 wva = *(const ulonglong2*)&Wvs[c*64 + g*8];
                ulonglong2 wvb = *(const ulonglong2*)&Wvs[c*64 + g*8 + 4];
                aq[0] = ffma2(xx, wqa.x, aq[0]);
                aq[1] = ffma2(xx, wqa.y, aq[1]);
                aq[2] = ffma2(xx, wqb.x, aq[2]);
                aq[3] = ffma2(xx, wqb.y, aq[3]);
                ak[0] = ffma2(xx, wka.x, ak[0]);
                ak[1] = ffma2(xx, wka.y, ak[1]);
                ak[2] = ffma2(xx, wkb.x, ak[2]);
                ak[3] = ffma2(xx, wkb.y, ak[3]);
                av[0] = ffma2(xx, wva.x, av[0]);
                av[1] = ffma2(xx, wva.y, av[1]);
                av[2] = ffma2(xx, wvb.x, av[2]);
                av[3] = ffma2(xx, wvb.y, av[3]);
            }
            *(ulonglong2*)&qs[t*68 + g*8]     = make_ulonglong2(aq[0], aq[1]);
            *(ulonglong2*)&qs[t*68 + g*8 + 4] = make_ulonglong2(aq[2], aq[3]);
            *(ulonglong2*)&ks[t*68 + g*8]     = make_ulonglong2(ak[0], ak[1]);
            *(ulonglong2*)&ks[t*68 + g*8 + 4] = make_ulonglong2(ak[2], ak[3]);
            *(ulonglong2*)&vs[t*68 + g*8]     = make_ulonglong2(av[0], av[1]);
            *(ulonglong2*)&vs[t*68 + g*8 + 4] = make_ulonglong2(av[2], av[3]);
        }
        __syncthreads();

        // ---- dots + softmax: row t handled by its 8-lane group, thread owns j = g+8u ----
        // FULL head dim: 64 floats = 16 ulonglong2 per row (was 8 -> bug)
        {
            u64 qreg[32];
            const ulonglong2* qrow = (const ulonglong2*)&qs[t*68];
            #pragma unroll
            for (int d = 0; d < 16; ++d) {
                ulonglong2 v2 = qrow[d];
                qreg[2*d] = v2.x; qreg[2*d+1] = v2.y;
            }
            float dv[4];
            #pragma unroll
            for (int u = 0; u < 4; ++u) {
                const ulonglong2* krow = (const ulonglong2*)&ks[(g + 8*u)*68];
                u64 acc0 = 0, acc1 = 0;
                #pragma unroll
                for (int d = 0; d < 16; ++d) {
                    ulonglong2 kv = krow[d];
                    acc0 = ffma2(qreg[2*d],   kv.x, acc0);
                    acc1 = ffma2(qreg[2*d+1], kv.y, acc1);
                }
                float l0, h0, l1, h1;
                unpack2(acc0, l0, h0); unpack2(acc1, l1, h1);
                dv[u] = ((l0 + h0) + (l1 + h1)) * 0.125f;   // * DIM_HEAD^-0.5
            }
            float mx = fmaxf(fmaxf(dv[0], dv[1]), fmaxf(dv[2], dv[3]));
            mx = fmaxf(mx, __shfl_xor_sync(0xffffffffu, mx, 1));
            mx = fmaxf(mx, __shfl_xor_sync(0xffffffffu, mx, 2));
            mx = fmaxf(mx, __shfl_xor_sync(0xffffffffu, mx, 4));
            float ev[4], s = 0.f;
            #pragma unroll
            for (int u = 0; u < 4; ++u) { ev[u] = __expf(dv[u] - mx); s += ev[u]; }
            s += __shfl_xor_sync(0xffffffffu, s, 1);
            s += __shfl_xor_sync(0xffffffffu, s, 2);
            s += __shfl_xor_sync(0xffffffffu, s, 4);
            float inv = 1.f / s;
            #pragma unroll
            for (int u = 0; u < 4; ++u) attnS[t*36 + g + 8*u] = ev[u] * inv;
        }
        __syncwarp();   // attn row t produced entirely within this warp's 8-lane group

        // ---- out = attn @ v, write straight to global scratch ----
        {
            u64 ao[4] = {0,0,0,0};
            #pragma unroll
            for (int j = 0; j < NKN; ++j) {
                float a = attnS[t*36 + j];
                u64 aa = pack2(a, a);
                ulonglong2 va = *(const ulonglong2*)&vs[j*68 + g*8];
                ulonglong2 vb = *(const ulonglong2*)&vs[j*68 + g*8 + 4];
                ao[0] = ffma2(aa, va.x, ao[0]);
                ao[1] = ffma2(aa, va.y, ao[1]);
                ao[2] = ffma2(aa, vb.x, ao[2]);
                ao[3] = ffma2(aa, vb.y, ao[3]);
            }
            float* op = &g_oatt[((size_t)pt*NKN + t)*INNERD + h*DH + g*8];
            *(ulonglong2*)op       = make_ulonglong2(ao[0], ao[1]);
            *(ulonglong2*)(op + 4) = make_ulonglong2(ao[2], ao[3]);
        }
    }
}

// ---------------- K4: output GEMM  y[131072,256] = oatt[131072,512] @ Wout + bout ----------------
__global__ __launch_bounds__(256, 2) void out_gemm_kernel(
    const float* __restrict__ Wout,
    const float* __restrict__ bout,
    float* __restrict__ y)
{
    __shared__ float As[16][132];   // [k][m] transposed, padded
    __shared__ float Bs[16][128];   // [k][n]
    const int tid = threadIdx.x;
    const int tx = tid & 15, ty = tid >> 4;
    const size_t m0 = (size_t)blockIdx.x * 128;
    const int n0 = blockIdx.y * 128;

    u64 acc[8][4] = {};
    for (int k0 = 0; k0 < INNERD; k0 += 16) {
        #pragma unroll
        for (int i = 0; i < 2; ++i) {
            int f = tid + i*256;
            int r = f >> 2, kc = (f & 3) << 2;
            float4 v = *(const float4*)&g_oatt[(m0 + r)*INNERD + (k0 + kc)];
            As[kc+0][r] = v.x; As[kc+1][r] = v.y; As[kc+2][r] = v.z; As[kc+3][r] = v.w;
            int rk = f >> 5, c = (f & 31) << 2;
            *(float4*)&Bs[rk][c] = *(const float4*)&Wout[(size_t)(k0 + rk)*DIMC + n0 + c];
        }
        __syncthreads();
        #pragma unroll
        for (int kk = 0; kk < 16; ++kk) {
            float a[8];
            *(float4*)&a[0] = *(const float4*)&As[kk][ty*8];
            *(float4*)&a[4] = *(const float4*)&As[kk][ty*8 + 4];
            ulonglong2 b0 = *(const ulonglong2*)&Bs[kk][tx*8];
            ulonglong2 b1 = *(const ulonglong2*)&Bs[kk][tx*8 + 4];
            #pragma unroll
            for (int i = 0; i < 8; ++i) {
                u64 aa = pack2(a[i], a[i]);
                acc[i][0] = ffma2(aa, b0.x, acc[i][0]);
                acc[i][1] = ffma2(aa, b0.y, acc[i][1]);
                acc[i][2] = ffma2(aa, b1.x, acc[i][2]);
                acc[i][3] = ffma2(aa, b1.y, acc[i][3]);
            }
        }
        __syncthreads();
    }
    float bo[8];
    #pragma unroll
    for (int u = 0; u < 8; ++u) bo[u] = bout[n0 + tx*8 + u];
    #pragma unroll
    for (int i = 0; i < 8; ++i) {
        float o[8];
        unpack2(acc[i][0], o[0], o[1]);
        unpack2(acc[i][1], o[2], o[3]);
        unpack2(acc[i][2], o[4], o[5]);
        unpack2(acc[i][3], o[6], o[7]);
        #pragma unroll
        for (int u = 0; u < 8; ++u) o[u] += bo[u];
        float* yp = &y[(m0 + ty*8 + i)*DIMC + n0 + tx*8];
        *(float4*)yp       = make_float4(o[0], o[1], o[2], o[3]);
        *(float4*)(yp + 4) = make_float4(o[4], o[5], o[6], o[7]);
    }
}

// ---------------- launcher ----------------
extern "C" void kernel_launch(void* const* d_in, const int* in_sizes, int n_in,
                              void* d_out, int out_size) {
    const float* x     = (const float*)d_in[0];
    const float* gamma = (const float*)d_in[1];
    const float* beta  = (const float*)d_in[2];
    const float* Wq    = (const float*)d_in[3];
    const float* Wk    = (const float*)d_in[4];
    const float* Wv    = (const float*)d_in[5];
    const float* Wout  = (const float*)d_in[6];
    const float* bout  = (const float*)d_in[7];
    float* y = (float*)d_out;

    cudaFuncSetAttribute(attn_kernel, cudaFuncAttributeMaxDynamicSharedMemorySize,
                         ATTN_SMEM_BYTES);

    bn_zero_kernel<<<1, 256>>>();
    bn_stats_kernel<<<512, 256>>>((const float4*)x);
    bn_finalize_kernel<<<1, 256>>>(gamma, beta);
    attn_kernel<<<NPTS, 256, ATTN_SMEM_BYTES>>>(x, Wq, Wk, Wv);
    out_gemm_kernel<<<dim3(NTOK/128, DIMC/128), 256>>>(Wout, bout, y);
}

// round 4
// speedup vs baseline: 5.6097x; 5.6097x over previous
#include <cuda_runtime.h>

// Problem constants
#define NB     4
#define NP     1024
#define NKN    32
#define DIMC   256
#define HEADS  8
#define DH     64
#define DPG    32
#define INNERD 512
#define NPTS   (NB*NP)        // 4096 points
#define NTOK   (NPTS*NKN)     // 131072 tokens

// ---------------- device scratch (no allocations allowed) ----------------
__device__ float g_sum[DIMC];
__device__ float g_sumsq[DIMC];
__device__ float g_scale[DIMC];
__device__ float g_shift[DIMC];
__device__ float g_oatt[(size_t)NTOK * INNERD];   // 268 MB attention output scratch (tf32-rounded)

// ---------------- tf32 helpers ----------------
__device__ __forceinline__ float tf32r(float x) {           // round-to-nearest tf32, kept in f32 container
    unsigned u; asm("cvt.rna.tf32.f32 %0, %1;" : "=r"(u) : "f"(x));
    return __uint_as_float(u);
}
__device__ __forceinline__ unsigned fbits(float x) { return __float_as_uint(x); }

__device__ __forceinline__ void mma_tf32(float c[4], const unsigned a[4], const unsigned b[2]) {
    asm volatile("mma.sync.aligned.m16n8k8.row.col.f32.tf32.tf32.f32 "
                 "{%0,%1,%2,%3}, {%4,%5,%6,%7}, {%8,%9}, {%0,%1,%2,%3};"
                 : "+f"(c[0]), "+f"(c[1]), "+f"(c[2]), "+f"(c[3])
                 : "r"(a[0]), "r"(a[1]), "r"(a[2]), "r"(a[3]), "r"(b[0]), "r"(b[1]));
}

// ---------------- K0: zero BN accumulators ----------------
__global__ void bn_zero_kernel() {
    g_sum[threadIdx.x] = 0.f;
    g_sumsq[threadIdx.x] = 0.f;
}

// ---------------- K1: BN statistics ----------------
__global__ __launch_bounds__(256) void bn_stats_kernel(const float4* __restrict__ x4) {
    const int tid = threadIdx.x;
    const int c64 = tid & 63;
    const int rl  = tid >> 6;
    const size_t base = (size_t)blockIdx.x * 256 + (size_t)rl * 64;
    float4 s = make_float4(0.f,0.f,0.f,0.f);
    float4 q = make_float4(0.f,0.f,0.f,0.f);
    #pragma unroll 4
    for (int i = 0; i < 64; ++i) {
        float4 v = x4[(base + i) * 64 + c64];
        s.x += v.x; s.y += v.y; s.z += v.z; s.w += v.w;
        q.x += v.x*v.x; q.y += v.y*v.y; q.z += v.z*v.z; q.w += v.w*v.w;
    }
    __shared__ float4 ss[256], qq[256];
    ss[tid] = s; qq[tid] = q;
    __syncthreads();
    if (tid < 64) {
        float4 a = ss[tid], b = ss[tid+64], c2 = ss[tid+128], d = ss[tid+192];
        float4 e = qq[tid], f = qq[tid+64], g2 = qq[tid+128], h = qq[tid+192];
        atomicAdd(&g_sum[tid*4+0], a.x+b.x+c2.x+d.x);
        atomicAdd(&g_sum[tid*4+1], a.y+b.y+c2.y+d.y);
        atomicAdd(&g_sum[tid*4+2], a.z+b.z+c2.z+d.z);
        atomicAdd(&g_sum[tid*4+3], a.w+b.w+c2.w+d.w);
        atomicAdd(&g_sumsq[tid*4+0], e.x+f.x+g2.x+h.x);
        atomicAdd(&g_sumsq[tid*4+1], e.y+f.y+g2.y+h.y);
        atomicAdd(&g_sumsq[tid*4+2], e.z+f.z+g2.z+h.z);
        atomicAdd(&g_sumsq[tid*4+3], e.w+f.w+g2.w+h.w);
    }
}

// ---------------- K2: BN finalize ----------------
__global__ void bn_finalize_kernel(const float* __restrict__ gamma,
                                   const float* __restrict__ beta) {
    const int c = threadIdx.x;
    const float invN = 1.f / (float)NTOK;
    float m   = g_sum[c] * invN;
    float var = g_sumsq[c] * invN - m * m;
    float rstd = rsqrtf(var + 1e-5f);
    float sc = gamma[c] * rstd;
    g_scale[c] = sc;
    g_shift[c] = beta[c] - m * sc;
}

// ---------------- K3: fused QKV + attention via tf32 mma.sync ----------------
// Block = 1 point, 256 threads = 8 warps, all warps cooperate per head.
// All smem row strides are == 4 (mod 32) so fragment LDS is bank-conflict-free.
// floats: xn 32*260 + qs 32*68 + ks 32*68 + vT 64*36 + Wh 3*64*36 + attnS 32*36 = 23040
#define ATTN_SMEM_FLOATS 23040
#define ATTN_SMEM_BYTES (ATTN_SMEM_FLOATS * 4)

__global__ __launch_bounds__(256, 2) void attn_mma_kernel(
    const float* __restrict__ x,
    const float* __restrict__ Wq,
    const float* __restrict__ Wk,
    const float* __restrict__ Wv)
{
    extern __shared__ float sm[];
    float* xn    = sm;                  // [32][260] tokens x channels (tf32-rounded)
    float* qs    = xn + 32*260;         // [32][68]
    float* ks    = qs + 32*68;          // [32][68]
    float* vT    = ks + 32*68;          // [64][36]  (transposed: [out][token])
    float* Wh    = vT + 64*36;          // [3][64][36] this head's W (tf32-rounded)
    float* attnS = Wh + 3*64*36;        // [32][36]

    const int tid  = threadIdx.x;
    const int warp = tid >> 5;
    const int lane = tid & 31;
    const int g4   = lane >> 2;   // groupID 0..7
    const int tg   = lane & 3;    // thread-in-group 0..3
    const int pt   = blockIdx.x;
    const float* xp = x + (size_t)pt * (NKN * DIMC);

    // Load, normalize, round to tf32
    {
        const float sc = g_scale[tid];
        const float sh = g_shift[tid];
        #pragma unroll 8
        for (int tk = 0; tk < NKN; ++tk)
            xn[tk*260 + tid] = tf32r(fmaf(xp[tk*DIMC + tid], sc, sh));
    }

    for (int h = 0; h < HEADS; ++h) {
        __syncthreads();   // xn ready / previous head fully consumed

        // ---- stage this head's Wq,Wk,Wv into smem (tf32-rounded) ----
        {
            const float* Wsrc0 = Wq + h*(DH*DPG);
            const float* Wsrc1 = Wk + h*(DH*DPG);
            const float* Wsrc2 = Wv + h*(DH*DPG);
            #pragma unroll
            for (int i = tid; i < DH*DPG; i += 256) {
                int o = i >> 5, c = i & 31;
                Wh[0*2304 + o*36 + c] = tf32r(Wsrc0[i]);
                Wh[1*2304 + o*36 + c] = tf32r(Wsrc1[i]);
                Wh[2*2304 + o*36 + c] = tf32r(Wsrc2[i]);
            }
        }
        __syncthreads();

        // ---- projections: warp w computes ntile=w (8 out-cols) for q,k,v ----
        {
            // A fragments from xn (shared across the 3 projections)
            unsigned a[2][4][4];
            #pragma unroll
            for (int mt = 0; mt < 2; ++mt)
                #pragma unroll
                for (int kt = 0; kt < 4; ++kt) {
                    const float* ap = &xn[(mt*16 + g4)*260 + h*DPG + kt*8 + tg];
                    a[mt][kt][0] = fbits(ap[0]);
                    a[mt][kt][1] = fbits(ap[8*260]);
                    a[mt][kt][2] = fbits(ap[4]);
                    a[mt][kt][3] = fbits(ap[8*260 + 4]);
                }
            #pragma unroll
            for (int pr = 0; pr < 3; ++pr) {
                unsigned b[4][2];
                #pragma unroll
                for (int kt = 0; kt < 4; ++kt) {
                    const float* bp = &Wh[pr*2304 + (warp*8 + g4)*36 + kt*8 + tg];
                    b[kt][0] = fbits(bp[0]);
                    b[kt][1] = fbits(bp[4]);
                }
                float c0[4] = {0,0,0,0}, c1[4] = {0,0,0,0};
                #pragma unroll
                for (int kt = 0; kt < 4; ++kt) {
                    mma_tf32(c0, a[0][kt], b[kt]);
                    mma_tf32(c1, a[1][kt], b[kt]);
                }
                const int col = warp*8 + 2*tg;
                if (pr < 2) {
                    float* dst = (pr == 0) ? qs : ks;
                    float* d0 = &dst[(g4)*68 + col];
                    float* d1 = &dst[(g4+8)*68 + col];
                    d0[0] = tf32r(c0[0]); d0[1] = tf32r(c0[1]);
                    d1[0] = tf32r(c0[2]); d1[1] = tf32r(c0[3]);
                    d0[16*68] = tf32r(c1[0]); d0[16*68+1] = tf32r(c1[1]);
                    d1[16*68] = tf32r(c1[2]); d1[16*68+1] = tf32r(c1[3]);
                } else {
                    // v transposed: vT[o][t]
                    vT[(col  )*36 + g4     ] = tf32r(c0[0]);
                    vT[(col+1)*36 + g4     ] = tf32r(c0[1]);
                    vT[(col  )*36 + g4 + 8 ] = tf32r(c0[2]);
                    vT[(col+1)*36 + g4 + 8 ] = tf32r(c0[3]);
                    vT[(col  )*36 + g4 + 16] = tf32r(c1[0]);
                    vT[(col+1)*36 + g4 + 16] = tf32r(c1[1]);
                    vT[(col  )*36 + g4 + 24] = tf32r(c1[2]);
                    vT[(col+1)*36 + g4 + 24] = tf32r(c1[3]);
                }
            }
        }
        __syncthreads();

        // ---- dots = (q @ k^T) * scale : warp w -> (mtile = w>>2, ntile = w&3) ----
        {
            const int mt = warp >> 2, nt = warp & 3;
            unsigned qa[8][4], kb[8][2];
            #pragma unroll
            for (int kt = 0; kt < 8; ++kt) {
                const float* ap = &qs[(mt*16 + g4)*68 + kt*8 + tg];
                qa[kt][0] = fbits(ap[0]);
                qa[kt][1] = fbits(ap[8*68]);
                qa[kt][2] = fbits(ap[4]);
                qa[kt][3] = fbits(ap[8*68 + 4]);
                const float* bp = &ks[(nt*8 + g4)*68 + kt*8 + tg];
                kb[kt][0] = fbits(bp[0]);
                kb[kt][1] = fbits(bp[4]);
            }
            float c[4] = {0,0,0,0};
            #pragma unroll
            for (int kt = 0; kt < 8; ++kt) mma_tf32(c, qa[kt], kb[kt]);
            const int r0 = mt*16 + g4, col = nt*8 + 2*tg;
            attnS[r0*36 + col]       = c[0] * 0.125f;
            attnS[r0*36 + col + 1]   = c[1] * 0.125f;
            attnS[(r0+8)*36 + col]   = c[2] * 0.125f;
            attnS[(r0+8)*36 + col+1] = c[3] * 0.125f;
        }
        __syncthreads();

        // ---- softmax rows: warp w owns rows 4w..4w+3; 8 lanes per row ----
        {
            const int r  = 4*warp + (lane >> 3);
            const int jb = lane & 7;
            float dv[4];
            #pragma unroll
            for (int u = 0; u < 4; ++u) dv[u] = attnS[r*36 + jb + 8*u];
            float mx = fmaxf(fmaxf(dv[0], dv[1]), fmaxf(dv[2], dv[3]));
            mx = fmaxf(mx, __shfl_xor_sync(0xffffffffu, mx, 1));
            mx = fmaxf(mx, __shfl_xor_sync(0xffffffffu, mx, 2));
            mx = fmaxf(mx, __shfl_xor_sync(0xffffffffu, mx, 4));
            float ev[4], s = 0.f;
            #pragma unroll
            for (int u = 0; u < 4; ++u) { ev[u] = __expf(dv[u] - mx); s += ev[u]; }
            s += __shfl_xor_sync(0xffffffffu, s, 1);
            s += __shfl_xor_sync(0xffffffffu, s, 2);
            s += __shfl_xor_sync(0xffffffffu, s, 4);
            float inv = 1.f / s;
            #pragma unroll
            for (int u = 0; u < 4; ++u) attnS[r*36 + jb + 8*u] = tf32r(ev[u] * inv);
        }
        __syncthreads();

        // ---- out = attn @ v : warp w -> (mtile = w>>2, ntiles = (w&3)*2 + {0,1}) ----
        {
            const int mt = warp >> 2;
            unsigned aa[4][4];
            #pragma unroll
            for (int kt = 0; kt < 4; ++kt) {
                const float* ap = &attnS[(mt*16 + g4)*36 + kt*8 + tg];
                aa[kt][0] = fbits(ap[0]);
                aa[kt][1] = fbits(ap[8*36]);
                aa[kt][2] = fbits(ap[4]);
                aa[kt][3] = fbits(ap[8*36 + 4]);
            }
            #pragma unroll
            for (int nn = 0; nn < 2; ++nn) {
                const int nt = (warp & 3)*2 + nn;
                unsigned vb[4][2];
                #pragma unroll
                for (int kt = 0; kt < 4; ++kt) {
                    const float* bp = &vT[(nt*8 + g4)*36 + kt*8 + tg];
                    vb[kt][0] = fbits(bp[0]);
                    vb[kt][1] = fbits(bp[4]);
                }
                float c[4] = {0,0,0,0};
                #pragma unroll
                for (int kt = 0; kt < 4; ++kt) mma_tf32(c, aa[kt], vb[kt]);
                // store (tf32-rounded: feeds out-GEMM A operand directly)
                const size_t row0 = (size_t)pt*NKN + mt*16 + g4;
                const int col = h*DH + nt*8 + 2*tg;
                float2 v0 = make_float2(tf32r(c[0]), tf32r(c[1]));
                float2 v1 = make_float2(tf32r(c[2]), tf32r(c[3]));
                *(float2*)&g_oatt[row0*INNERD + col]       = v0;
                *(float2*)&g_oatt[(row0+8)*INNERD + col]   = v1;
            }
        }
    }
}

// ---------------- K4: output GEMM via tf32 mma.sync ----------------
// y[NTOK,256] = oatt[NTOK,512] @ Wout + bout. Block tile 128x128, warp tile 32x64.
__global__ __launch_bounds__(256, 2) void out_gemm_mma(
    const float* __restrict__ Wout,
    const float* __restrict__ bout,
    float* __restrict__ y)
{
    __shared__ float As[128*36];     // [m][k] stride 36
    __shared__ float Bs[32*136];     // [k][n] stride 136 (8 mod 32 -> conflict-free b-frags)
    const int tid  = threadIdx.x;
    const int warp = tid >> 5;
    const int lane = tid & 31;
    const int g4   = lane >> 2;
    const int tg   = lane & 3;
    const size_t m0 = (size_t)blockIdx.x * 128;
    const int n0 = blockIdx.y * 128;
    const int mw = (warp >> 1) * 32;
    const int nw = (warp & 1) * 64;

    float acc[2][8][4] = {};

    for (int k0 = 0; k0 < INNERD; k0 += 32) {
        // stage A (oatt, already tf32-rounded): 128x32
        {
            const int r = tid >> 3, c = (tid & 7) * 4;
            #pragma unroll
            for (int i = 0; i < 4; ++i) {
                float4 v = *(const float4*)&g_oatt[(m0 + r + i*32)*INNERD + k0 + c];
                *(float4*)&As[(r + i*32)*36 + c] = v;
            }
            // stage B (Wout) with tf32 rounding: 32x128
            const int rb = tid >> 5, cb = (tid & 31) * 4;
            #pragma unroll
            for (int i = 0; i < 4; ++i) {
                float4 v = *(const float4*)&Wout[(size_t)(k0 + rb + i*8)*DIMC + n0 + cb];
                v.x = tf32r(v.x); v.y = tf32r(v.y); v.z = tf32r(v.z); v.w = tf32r(v.w);
                *(float4*)&Bs[(rb + i*8)*136 + cb] = v;
            }
        }
        __syncthreads();
        #pragma unroll
        for (int kf = 0; kf < 4; ++kf) {
            unsigned a[2][4], b[8][2];
            #pragma unroll
            for (int mt = 0; mt < 2; ++mt) {
                const float* ap = &As[(mw + mt*16 + g4)*36 + kf*8 + tg];
                a[mt][0] = fbits(ap[0]);
                a[mt][1] = fbits(ap[8*36]);
                a[mt][2] = fbits(ap[4]);
                a[mt][3] = fbits(ap[8*36 + 4]);
            }
            #pragma unroll
            for (int nt = 0; nt < 8; ++nt) {
                const float* bp = &Bs[(kf*8 + tg)*136 + nw + nt*8 + g4];
                b[nt][0] = fbits(bp[0]);
                b[nt][1] = fbits(bp[4*136]);
            }
            #pragma unroll
            for (int mt = 0; mt < 2; ++mt)
                #pragma unroll
                for (int nt = 0; nt < 8; ++nt)
                    mma_tf32(acc[mt][nt], a[mt], b[nt]);
        }
        __syncthreads();
    }

    // epilogue: add bias, store
    #pragma unroll
    for (int nt = 0; nt < 8; ++nt) {
        const int cn = n0 + nw + nt*8 + 2*tg;
        float2 bo = *(const float2*)&bout[cn];
        #pragma unroll
        for (int mt = 0; mt < 2; ++mt) {
            const size_t r0 = m0 + mw + mt*16 + g4;
            float2 o0 = make_float2(acc[mt][nt][0] + bo.x, acc[mt][nt][1] + bo.y);
            float2 o1 = make_float2(acc[mt][nt][2] + bo.x, acc[mt][nt][3] + bo.y);
            *(float2*)&y[r0*DIMC + cn]       = o0;
            *(float2*)&y[(r0+8)*DIMC + cn]   = o1;
        }
    }
}

// ---------------- launcher ----------------
extern "C" void kernel_launch(void* const* d_in, const int* in_sizes, int n_in,
                              void* d_out, int out_size) {
    const float* x     = (const float*)d_in[0];
    const float* gamma = (const float*)d_in[1];
    const float* beta  = (const float*)d_in[2];
    const float* Wq    = (const float*)d_in[3];
    const float* Wk    = (const float*)d_in[4];
    const float* Wv    = (const float*)d_in[5];
    const float* Wout  = (const float*)d_in[6];
    const float* bout  = (const float*)d_in[7];
    float* y = (float*)d_out;

    cudaFuncSetAttribute(attn_mma_kernel, cudaFuncAttributeMaxDynamicSharedMemorySize,
                         ATTN_SMEM_BYTES);

    bn_zero_kernel<<<1, 256>>>();
    bn_stats_kernel<<<512, 256>>>((const float4*)x);
    bn_finalize_kernel<<<1, 256>>>(gamma, beta);
    attn_mma_kernel<<<NPTS, 256, ATTN_SMEM_BYTES>>>(x, Wq, Wk, Wv);
    out_gemm_mma<<<dim3(NTOK/128, DIMC/128), 256>>>(Wout, bout, y);
}

// round 5
// speedup vs baseline: 6.8201x; 1.2158x over previous
#include <cuda_runtime.h>

// Problem constants
#define NB     4
#define NP     1024
#define NKN    32
#define DIMC   256
#define HEADS  8
#define DH     64
#define DPG    32
#define INNERD 512
#define NPTS   (NB*NP)        // 4096 points
#define NTOK   (NPTS*NKN)     // 131072 tokens

// ---------------- device scratch (no allocations allowed) ----------------
__device__ float g_sum[DIMC];
__device__ float g_sumsq[DIMC];
__device__ float g_scale[DIMC];
__device__ float g_shift[DIMC];
__device__ float g_oatt[(size_t)NTOK * INNERD];   // 268 MB attention output (tf32-rounded)
__device__ float g_wq[HEADS*DH*DPG];              // tf32-rounded weights
__device__ float g_wk[HEADS*DH*DPG];
__device__ float g_wv[HEADS*DH*DPG];
__device__ float g_wout[INNERD*DIMC];

// ---------------- tf32 / mma helpers ----------------
__device__ __forceinline__ float tf32r(float x) {
    unsigned u; asm("cvt.rna.tf32.f32 %0, %1;" : "=r"(u) : "f"(x));
    return __uint_as_float(u);
}
__device__ __forceinline__ unsigned fbits(float x) { return __float_as_uint(x); }

__device__ __forceinline__ void mma_tf32(float c[4], const unsigned a[4], const unsigned b[2]) {
    asm volatile("mma.sync.aligned.m16n8k8.row.col.f32.tf32.tf32.f32 "
                 "{%0,%1,%2,%3}, {%4,%5,%6,%7}, {%8,%9}, {%0,%1,%2,%3};"
                 : "+f"(c[0]), "+f"(c[1]), "+f"(c[2]), "+f"(c[3])
                 : "r"(a[0]), "r"(a[1]), "r"(a[2]), "r"(a[3]), "r"(b[0]), "r"(b[1]));
}

__device__ __forceinline__ void cpa16(unsigned s, const void* g) {
    asm volatile("cp.async.cg.shared.global [%0], [%1], 16;" :: "r"(s), "l"(g));
}
__device__ __forceinline__ void cpa_commit() { asm volatile("cp.async.commit_group;"); }
template<int N> __device__ __forceinline__ void cpa_wait() {
    asm volatile("cp.async.wait_group %0;" :: "n"(N));
}

// ---------------- K0: zero BN accumulators ----------------
__global__ void bn_zero_kernel() {
    g_sum[threadIdx.x] = 0.f;
    g_sumsq[threadIdx.x] = 0.f;
}

// ---------------- K1: BN statistics ----------------
__global__ __launch_bounds__(256) void bn_stats_kernel(const float4* __restrict__ x4) {
    const int tid = threadIdx.x;
    const int c64 = tid & 63;
    const int rl  = tid >> 6;
    const size_t base = (size_t)blockIdx.x * 256 + (size_t)rl * 64;
    float4 s = make_float4(0.f,0.f,0.f,0.f);
    float4 q = make_float4(0.f,0.f,0.f,0.f);
    #pragma unroll 4
    for (int i = 0; i < 64; ++i) {
        float4 v = x4[(base + i) * 64 + c64];
        s.x += v.x; s.y += v.y; s.z += v.z; s.w += v.w;
        q.x += v.x*v.x; q.y += v.y*v.y; q.z += v.z*v.z; q.w += v.w*v.w;
    }
    __shared__ float4 ss[256], qq[256];
    ss[tid] = s; qq[tid] = q;
    __syncthreads();
    if (tid < 64) {
        float4 a = ss[tid], b = ss[tid+64], c2 = ss[tid+128], d = ss[tid+192];
        float4 e = qq[tid], f = qq[tid+64], g2 = qq[tid+128], h = qq[tid+192];
        atomicAdd(&g_sum[tid*4+0], a.x+b.x+c2.x+d.x);
        atomicAdd(&g_sum[tid*4+1], a.y+b.y+c2.y+d.y);
        atomicAdd(&g_sum[tid*4+2], a.z+b.z+c2.z+d.z);
        atomicAdd(&g_sum[tid*4+3], a.w+b.w+c2.w+d.w);
        atomicAdd(&g_sumsq[tid*4+0], e.x+f.x+g2.x+h.x);
        atomicAdd(&g_sumsq[tid*4+1], e.y+f.y+g2.y+h.y);
        atomicAdd(&g_sumsq[tid*4+2], e.z+f.z+g2.z+h.z);
        atomicAdd(&g_sumsq[tid*4+3], e.w+f.w+g2.w+h.w);
    }
}

// ---------------- K2: BN finalize ----------------
__global__ void bn_finalize_kernel(const float* __restrict__ gamma,
                                   const float* __restrict__ beta) {
    const int c = threadIdx.x;
    const float invN = 1.f / (float)NTOK;
    float m   = g_sum[c] * invN;
    float var = g_sumsq[c] * invN - m * m;
    float rstd = rsqrtf(var + 1e-5f);
    float sc = gamma[c] * rstd;
    g_scale[c] = sc;
    g_shift[c] = beta[c] - m * sc;
}

// ---------------- K2b: pre-round weights to tf32 (once) ----------------
__global__ void round_weights_kernel(const float* __restrict__ Wq,
                                     const float* __restrict__ Wk,
                                     const float* __restrict__ Wv,
                                     const float* __restrict__ Wout) {
    int i = blockIdx.x * 256 + threadIdx.x;
    if (i < INNERD*DIMC) g_wout[i] = tf32r(Wout[i]);
    if (i < HEADS*DH*DPG) {
        g_wq[i] = tf32r(Wq[i]);
        g_wk[i] = tf32r(Wk[i]);
        g_wv[i] = tf32r(Wv[i]);
    }
}

// ---------------- K3: fused QKV + attention (2 points per block) ----------------
// smem floats: xh 64*36 + Wh 3*64*36 + qs 64*68 + ks 64*68 + vT 64*68 + attnS 64*36 = 24576
#define ATTN_SMEM_BYTES (24576 * 4)

__global__ __launch_bounds__(256, 2) void attn_mma2_kernel(const float* __restrict__ x)
{
    extern __shared__ float sm[];
    float* xh    = sm;                 // [64][36]  normalized tf32 slice (this head)
    float* Wh    = xh + 64*36;         // [3][64][36]
    float* qs    = Wh + 3*64*36;       // [64][68]
    float* ks    = qs + 64*68;         // [64][68]
    float* vT    = ks + 64*68;         // [64 out][68] (cols = 64 tokens)
    float* attnS = vT + 64*68;         // [64][36]

    const int tid  = threadIdx.x;
    const int warp = tid >> 5;
    const int lane = tid & 31;
    const int g4   = lane >> 2;
    const int tg   = lane & 3;
    const size_t tok0 = (size_t)blockIdx.x * 64;   // 2 points = 64 token rows

    for (int h = 0; h < HEADS; ++h) {
        // ---- stage Wh (pre-rounded) + xh (normalize + tf32) ----
        {
            const float* wq = g_wq + h*(DH*DPG);
            const float* wk = g_wk + h*(DH*DPG);
            const float* wv = g_wv + h*(DH*DPG);
            #pragma unroll
            for (int j = 0; j < 8; ++j) {
                int i = tid + j*256;               // 0..2047
                int o = i >> 5, c = i & 31;
                Wh[0*2304 + o*36 + c] = wq[i];
                Wh[1*2304 + o*36 + c] = wk[i];
                Wh[2*2304 + o*36 + c] = wv[i];
            }
            #pragma unroll
            for (int j = 0; j < 8; ++j) {
                int i = tid + j*256;               // 0..2047
                int tk = i >> 5, c = i & 31;
                float sc = g_scale[h*32 + c];
                float sh = g_shift[h*32 + c];
                xh[tk*36 + c] = tf32r(fmaf(x[(tok0 + tk)*DIMC + h*32 + c], sc, sh));
            }
        }
        __syncthreads();

        // ---- projections: warp = ntile (8 out cols), M=64 (4 mtiles) ----
        {
            unsigned a[4][4][4];                   // [mt][kt][frag]
            #pragma unroll
            for (int mt = 0; mt < 4; ++mt)
                #pragma unroll
                for (int kt = 0; kt < 4; ++kt) {
                    const float* ap = &xh[(mt*16 + g4)*36 + kt*8 + tg];
                    a[mt][kt][0] = fbits(ap[0]);
                    a[mt][kt][1] = fbits(ap[8*36]);
                    a[mt][kt][2] = fbits(ap[4]);
                    a[mt][kt][3] = fbits(ap[8*36 + 4]);
                }
            const int col = warp*8 + 2*tg;
            #pragma unroll
            for (int pr = 0; pr < 3; ++pr) {
                unsigned b[4][2];
                #pragma unroll
                for (int kt = 0; kt < 4; ++kt) {
                    const float* bp = &Wh[pr*2304 + (warp*8 + g4)*36 + kt*8 + tg];
                    b[kt][0] = fbits(bp[0]);
                    b[kt][1] = fbits(bp[4]);
                }
                float c[4][4] = {};
                #pragma unroll
                for (int kt = 0; kt < 4; ++kt)
                    #pragma unroll
                    for (int mt = 0; mt < 4; ++mt)
                        mma_tf32(c[mt], a[mt][kt], b[kt]);
                if (pr < 2) {
                    float* dst = (pr == 0) ? qs : ks;
                    #pragma unroll
                    for (int mt = 0; mt < 4; ++mt) {
                        int r = mt*16 + g4;
                        *(float2*)&dst[r*68 + col]     = make_float2(tf32r(c[mt][0]), tf32r(c[mt][1]));
                        *(float2*)&dst[(r+8)*68 + col] = make_float2(tf32r(c[mt][2]), tf32r(c[mt][3]));
                    }
                } else {
                    #pragma unroll
                    for (int mt = 0; mt < 4; ++mt) {
                        int r = mt*16 + g4;
                        vT[(col  )*68 + r]     = tf32r(c[mt][0]);
                        vT[(col+1)*68 + r]     = tf32r(c[mt][1]);
                        vT[(col  )*68 + r + 8] = tf32r(c[mt][2]);
                        vT[(col+1)*68 + r + 8] = tf32r(c[mt][3]);
                    }
                }
            }
        }
        __syncthreads();

        // ---- dots: warp -> (point p, mtile, n-half). K=64 (8 ktiles), 2 ntiles/warp ----
        {
            const int p  = warp >> 2;
            const int mt = (warp >> 1) & 1;
            const int nh = warp & 1;
            const int rbase = p*32 + mt*16;
            unsigned a[8][4];
            #pragma unroll
            for (int kt = 0; kt < 8; ++kt) {
                const float* ap = &qs[(rbase + g4)*68 + kt*8 + tg];
                a[kt][0] = fbits(ap[0]);
                a[kt][1] = fbits(ap[8*68]);
                a[kt][2] = fbits(ap[4]);
                a[kt][3] = fbits(ap[8*68 + 4]);
            }
            float c[2][4] = {};
            #pragma unroll
            for (int nn = 0; nn < 2; ++nn) {
                const int tokn = p*32 + (nh*2 + nn)*8;
                #pragma unroll
                for (int kt = 0; kt < 8; ++kt) {
                    const float* bp = &ks[(tokn + g4)*68 + kt*8 + tg];
                    unsigned b[2] = { fbits(bp[0]), fbits(bp[4]) };
                    mma_tf32(c[nn], a[kt], b);
                }
            }
            #pragma unroll
            for (int nn = 0; nn < 2; ++nn) {
                const int col = (nh*2 + nn)*8 + 2*tg;
                *(float2*)&attnS[(rbase + g4)*36 + col] =
                    make_float2(c[nn][0]*0.125f, c[nn][1]*0.125f);
                *(float2*)&attnS[(rbase + 8 + g4)*36 + col] =
                    make_float2(c[nn][2]*0.125f, c[nn][3]*0.125f);
            }
        }
        __syncthreads();

        // ---- softmax: warp owns rows warp*8..+8; 4 lanes per row (8 cols each) ----
        {
            const int r  = warp*8 + (lane >> 2);
            const int cq = lane & 3;
            float4 v0 = *(const float4*)&attnS[r*36 + cq*8];
            float4 v1 = *(const float4*)&attnS[r*36 + cq*8 + 4];
            float mx = fmaxf(fmaxf(fmaxf(v0.x, v0.y), fmaxf(v0.z, v0.w)),
                             fmaxf(fmaxf(v1.x, v1.y), fmaxf(v1.z, v1.w)));
            mx = fmaxf(mx, __shfl_xor_sync(0xffffffffu, mx, 1));
            mx = fmaxf(mx, __shfl_xor_sync(0xffffffffu, mx, 2));
            float e0 = __expf(v0.x - mx), e1 = __expf(v0.y - mx);
            float e2 = __expf(v0.z - mx), e3 = __expf(v0.w - mx);
            float e4 = __expf(v1.x - mx), e5 = __expf(v1.y - mx);
            float e6 = __expf(v1.z - mx), e7 = __expf(v1.w - mx);
            float s = ((e0+e1)+(e2+e3)) + ((e4+e5)+(e6+e7));
            s += __shfl_xor_sync(0xffffffffu, s, 1);
            s += __shfl_xor_sync(0xffffffffu, s, 2);
            float inv = 1.f / s;
            *(float4*)&attnS[r*36 + cq*8] =
                make_float4(tf32r(e0*inv), tf32r(e1*inv), tf32r(e2*inv), tf32r(e3*inv));
            *(float4*)&attnS[r*36 + cq*8 + 4] =
                make_float4(tf32r(e4*inv), tf32r(e5*inv), tf32r(e6*inv), tf32r(e7*inv));
        }
        __syncthreads();

        // ---- AV: warp -> (point p, mtile, n-quad of 32 cols); 4 ntiles/warp ----
        {
            const int p  = warp >> 2;
            const int mt = (warp >> 1) & 1;
            const int nq = warp & 1;
            const int rbase = p*32 + mt*16;
            unsigned a[4][4];
            #pragma unroll
            for (int kt = 0; kt < 4; ++kt) {
                const float* ap = &attnS[(rbase + g4)*36 + kt*8 + tg];
                a[kt][0] = fbits(ap[0]);
                a[kt][1] = fbits(ap[8*36]);
                a[kt][2] = fbits(ap[4]);
                a[kt][3] = fbits(ap[8*36 + 4]);
            }
            #pragma unroll
            for (int nt = 0; nt < 4; ++nt) {
                const int o = nq*32 + nt*8;
                float c[4] = {};
                #pragma unroll
                for (int kt = 0; kt < 4; ++kt) {
                    const float* bp = &vT[(o + g4)*68 + p*32 + kt*8 + tg];
                    unsigned b[2] = { fbits(bp[0]), fbits(bp[4]) };
                    mma_tf32(c, a[kt], b);
                }
                const size_t row = tok0 + rbase + g4;
                const int col = h*DH + o + 2*tg;
                *(float2*)&g_oatt[row*INNERD + col] =
                    make_float2(tf32r(c[0]), tf32r(c[1]));
                *(float2*)&g_oatt[(row+8)*INNERD + col] =
                    make_float2(tf32r(c[2]), tf32r(c[3]));
            }
        }
        __syncthreads();   // protects qs/ks/vT/attnS + xh/Wh rewrite next head
    }
}

// ---------------- K4: output GEMM, cp.async double-buffered ----------------
// y[NTOK,256] = oatt[NTOK,512] @ g_wout + bout. Block tile 128x128, warp tile 32x64.
#define GEMM_SMEM_BYTES ((2*(128*36) + 2*(32*136)) * 4)   // 71680 B

__global__ __launch_bounds__(256, 2) void out_gemm2_kernel(
    const float* __restrict__ bout,
    float* __restrict__ y)
{
    extern __shared__ float gsm[];
    float* As = gsm;                  // [2][128*36]
    float* Bs = gsm + 2*128*36;       // [2][32*136]

    const int tid  = threadIdx.x;
    const int warp = tid >> 5;
    const int lane = tid & 31;
    const int g4   = lane >> 2;
    const int tg   = lane & 3;
    const size_t m0 = (size_t)blockIdx.x * 128;
    const int n0 = blockIdx.y * 128;
    const int mw = (warp >> 1) * 32;
    const int nw = (warp & 1) * 64;

    const int ra = tid >> 3, ca = (tid & 7) * 4;     // A staging coords
    const int rb = tid >> 5, cb = (tid & 31) * 4;    // B staging coords

    unsigned smA = (unsigned)__cvta_generic_to_shared(As);
    unsigned smB = (unsigned)__cvta_generic_to_shared(Bs);

    // stage k-chunk into buffer buf
    auto stage = [&](int buf, int k0) {
        unsigned ab = smA + (unsigned)(buf*128*36*4);
        unsigned bb = smB + (unsigned)(buf*32*136*4);
        #pragma unroll
        for (int i = 0; i < 4; ++i)
            cpa16(ab + ((ra + i*32)*36 + ca)*4,
                  &g_oatt[(m0 + ra + i*32)*INNERD + k0 + ca]);
        #pragma unroll
        for (int i = 0; i < 4; ++i)
            cpa16(bb + ((rb + i*8)*136 + cb)*4,
                  &g_wout[(size_t)(k0 + rb + i*8)*DIMC + n0 + cb]);
    };

    float acc[2][8][4] = {};

    stage(0, 0);
    cpa_commit();

    #pragma unroll 1
    for (int it = 0; it < INNERD/32; ++it) {
        if (it + 1 < INNERD/32) {
            stage((it + 1) & 1, (it + 1)*32);
            cpa_commit();
            cpa_wait<1>();
        } else {
            cpa_wait<0>();
        }
        __syncthreads();

        const float* Ab = As + (it & 1)*128*36;
        const float* Bb = Bs + (it & 1)*32*136;
        #pragma unroll
        for (int kf = 0; kf < 4; ++kf) {
            unsigned a[2][4], b[8][2];
            #pragma unroll
            for (int mt = 0; mt < 2; ++mt) {
                const float* ap = &Ab[(mw + mt*16 + g4)*36 + kf*8 + tg];
                a[mt][0] = fbits(ap[0]);
                a[mt][1] = fbits(ap[8*36]);
                a[mt][2] = fbits(ap[4]);
                a[mt][3] = fbits(ap[8*36 + 4]);
            }
            #pragma unroll
            for (int nt = 0; nt < 8; ++nt) {
                const float* bp = &Bb[(kf*8 + tg)*136 + nw + nt*8 + g4];
                b[nt][0] = fbits(bp[0]);
                b[nt][1] = fbits(bp[4*136]);
            }
            #pragma unroll
            for (int mt = 0; mt < 2; ++mt)
                #pragma unroll
                for (int nt = 0; nt < 8; ++nt)
                    mma_tf32(acc[mt][nt], a[mt], b[nt]);
        }
        __syncthreads();
    }

    // epilogue: add bias, store
    #pragma unroll
    for (int nt = 0; nt < 8; ++nt) {
        const int cn = n0 + nw + nt*8 + 2*tg;
        float2 bo = *(const float2*)&bout[cn];
        #pragma unroll
        for (int mt = 0; mt < 2; ++mt) {
            const size_t r0 = m0 + mw + mt*16 + g4;
            *(float2*)&y[r0*DIMC + cn] =
                make_float2(acc[mt][nt][0] + bo.x, acc[mt][nt][1] + bo.y);
            *(float2*)&y[(r0+8)*DIMC + cn] =
                make_float2(acc[mt][nt][2] + bo.x, acc[mt][nt][3] + bo.y);
        }
    }
}

// ---------------- launcher ----------------
extern "C" void kernel_launch(void* const* d_in, const int* in_sizes, int n_in,
                              void* d_out, int out_size) {
    const float* x     = (const float*)d_in[0];
    const float* gamma = (const float*)d_in[1];
    const float* beta  = (const float*)d_in[2];
    const float* Wq    = (const float*)d_in[3];
    const float* Wk    = (const float*)d_in[4];
    const float* Wv    = (const float*)d_in[5];
    const float* Wout  = (const float*)d_in[6];
    const float* bout  = (const float*)d_in[7];
    float* y = (float*)d_out;

    cudaFuncSetAttribute(attn_mma2_kernel, cudaFuncAttributeMaxDynamicSharedMemorySize,
                         ATTN_SMEM_BYTES);
    cudaFuncSetAttribute(out_gemm2_kernel, cudaFuncAttributeMaxDynamicSharedMemorySize,
                         GEMM_SMEM_BYTES);

    bn_zero_kernel<<<1, 256>>>();
    bn_stats_kernel<<<512, 256>>>((const float4*)x);
    bn_finalize_kernel<<<1, 256>>>(gamma, beta);
    round_weights_kernel<<<(INNERD*DIMC + 255)/256, 256>>>(Wq, Wk, Wv, Wout);
    attn_mma2_kernel<<<NPTS/2, 256, ATTN_SMEM_BYTES>>>(x);
    out_gemm2_kernel<<<dim3(NTOK/128, DIMC/128), 256, GEMM_SMEM_BYTES>>>(bout, y);
}